// round 7
// baseline (speedup 1.0000x reference)
#include <cuda_runtime.h>
#include <math.h>
#include <stdint.h>

// ContrastiveLoss, B=4096, D=1024, MARGIN=1.0, EPS=1e-8.
//
// MARGIN == 1.0 makes the off-diagonal hinge relu(cos_ij - 1) identically 0
// for unit vectors, so the loss reduces exactly to the diagonal terms. We read
// only the labels diagonal and stream the 3 feature matrices (48 MB).
//
// R7: R1==R5 (10.75us at 43% vs 87% occ, any warp access order) proves the
// LDG path is pinned at ~4.6TB/s independent of SM-side knobs -> the limiter
// is the request stream itself (512B LDG requests, ~400K interleaved).
// Switch to cp.async.bulk: each block pulls 3 x 16KB contiguous chunks
// (4 rows per stream) gmem->smem via one mbarrier, computes from smem.
// Memory system sees ~3K large sequential requests (the path B300's measured
// ~6300B/cyc ceiling was obtained on).

#ifndef WARP_FULL_MASK
#define WARP_FULL_MASK 0xFFFFFFFFu
#endif

#define THREADS 128
#define NWARPS  (THREADS / 32)      // 4 warps
#define ROWS_PER_BLOCK 4
#define ROW_BYTES 4096              // D=1024 floats
#define STREAM_BYTES (ROWS_PER_BLOCK * ROW_BYTES)   // 16KB
#define SMEM_DATA (3 * STREAM_BYTES)                // 48KB
#define SMEM_TOTAL (SMEM_DATA + 16)                 // + mbarrier slot

static __device__ float g_partial[8192];   // per-row losses (B <= 8192)

__device__ __forceinline__ float warp_sum(float v) {
#pragma unroll
    for (int o = 16; o > 0; o >>= 1)
        v += __shfl_down_sync(WARP_FULL_MASK, v, o);
    return v;
}

__device__ __forceinline__ uint32_t smem_u32(const void* p) {
    uint32_t a;
    asm("{ .reg .u64 t; cvta.to.shared.u64 t, %1; cvt.u32.u64 %0, t; }"
        : "=r"(a) : "l"(p));
    return a;
}

__device__ __forceinline__ void mbar_init(uint32_t mbar, uint32_t cnt) {
    asm volatile("mbarrier.init.shared.b64 [%0], %1;" :: "r"(mbar), "r"(cnt) : "memory");
}
__device__ __forceinline__ void mbar_expect_tx(uint32_t mbar, uint32_t bytes) {
    asm volatile("mbarrier.arrive.expect_tx.shared.b64 _, [%0], %1;"
                 :: "r"(mbar), "r"(bytes) : "memory");
}
__device__ __forceinline__ void mbar_wait(uint32_t mbar, uint32_t parity) {
    uint32_t done;
    asm volatile(
        "{\n\t.reg .pred p;\n\t"
        "mbarrier.try_wait.parity.acquire.cta.shared::cta.b64 p, [%1], %2;\n\t"
        "selp.b32 %0, 1, 0, p;\n\t}"
        : "=r"(done) : "r"(mbar), "r"(parity) : "memory");
    if (!done) {
        asm volatile(
            "{\n\t.reg .pred P1;\n\t"
            "WAIT_LOOP_%=:\n\t"
            "mbarrier.try_wait.parity.acquire.cta.shared::cta.b64 P1, [%0], %1, 0x989680;\n\t"
            "@P1 bra.uni WAIT_DONE_%=;\n\t"
            "bra.uni WAIT_LOOP_%=;\n\t"
            "WAIT_DONE_%=:\n\t}"
            :: "r"(mbar), "r"(parity) : "memory");
    }
}
__device__ __forceinline__ void bulk_ld(uint32_t dst_smem, const void* src, uint32_t bytes, uint32_t mbar) {
    asm volatile(
        "cp.async.bulk.shared::cluster.global.mbarrier::complete_tx::bytes [%0], [%1], %2, [%3];"
        :: "r"(dst_smem), "l"(src), "r"(bytes), "r"(mbar) : "memory");
}

__device__ __forceinline__ void row_finish(float d0, float d1, float n0,
                                           float n1, float nt,
                                           const float* labels, int B, int row,
                                           int lane)
{
    d0 = warp_sum(d0); d1 = warp_sum(d1);
    n0 = warp_sum(n0); n1 = warp_sum(n1); nt = warp_sum(nt);
    if (lane == 0) {
        const float EPS = 1e-8f;
        float inv_t = 1.0f / fmaxf(sqrtf(nt), EPS);
        float cos0  = d0 * (1.0f / fmaxf(sqrtf(n0), EPS)) * inv_t;
        float cos1  = d1 * (1.0f / fmaxf(sqrtf(n1), EPS)) * inv_t;
        float L     = labels[(size_t)row * B + row];   // diagonal label
        g_partial[row] =
              L * (1.0f - cos0) + (1.0f - L) * fmaxf(cos0 - 1.0f, 0.0f)
            + L * (1.0f - cos1) + (1.0f - L) * fmaxf(cos1 - 1.0f, 0.0f);
    }
}

// Block = 4 consecutive rows. 3 bulk copies (16KB each) -> smem; warp w
// computes row w of the group from smem.
__global__ void __launch_bounds__(THREADS)
row_loss_tma_kernel(const float* __restrict__ f0,
                    const float* __restrict__ f1,
                    const float* __restrict__ t,
                    const float* __restrict__ labels,
                    int B)
{
    extern __shared__ __align__(16) char smem[];
    // layout: [f0: 16KB][f1: 16KB][t: 16KB][mbar: 8B]
    uint32_t mbar = smem_u32(smem + SMEM_DATA);

    int tid  = threadIdx.x;
    int lane = tid & 31;
    int wid  = tid >> 5;
    int grp  = blockIdx.x;
    size_t gbase = (size_t)grp * (STREAM_BYTES / 4);   // float offset of group

    if (tid == 0) {
        mbar_init(mbar, 1);
        // fence: make init visible to the async proxy before TMA targets it
        asm volatile("fence.proxy.async.shared::cta;" ::: "memory");
        mbar_expect_tx(mbar, 3 * STREAM_BYTES);
        bulk_ld(smem_u32(smem + 0 * STREAM_BYTES), f0 + gbase, STREAM_BYTES, mbar);
        bulk_ld(smem_u32(smem + 1 * STREAM_BYTES), f1 + gbase, STREAM_BYTES, mbar);
        bulk_ld(smem_u32(smem + 2 * STREAM_BYTES), t  + gbase, STREAM_BYTES, mbar);
    }
    __syncthreads();          // all threads see initialized mbarrier
    mbar_wait(mbar, 0);       // acquire: smem data visible after this

    int row = grp * ROWS_PER_BLOCK + wid;
    const float4* a4 = (const float4*)(smem + 0 * STREAM_BYTES + wid * ROW_BYTES);
    const float4* b4 = (const float4*)(smem + 1 * STREAM_BYTES + wid * ROW_BYTES);
    const float4* c4 = (const float4*)(smem + 2 * STREAM_BYTES + wid * ROW_BYTES);

    float d0 = 0.f, d1 = 0.f, n0 = 0.f, n1 = 0.f, nt = 0.f;
#pragma unroll
    for (int i = 0; i < (ROW_BYTES / 16) / 32; i++) {   // 8 iters
        int idx = lane + i * 32;
        float4 a = a4[idx];
        float4 b = b4[idx];
        float4 c = c4[idx];
        d0 += a.x * c.x + a.y * c.y + a.z * c.z + a.w * c.w;
        d1 += b.x * c.x + b.y * c.y + b.z * c.z + b.w * c.w;
        n0 += a.x * a.x + a.y * a.y + a.z * a.z + a.w * a.w;
        n1 += b.x * b.x + b.y * b.y + b.z * b.z + b.w * b.w;
        nt += c.x * c.x + c.y * c.y + c.z * c.z + c.w * c.w;
    }
    row_finish(d0, d1, n0, n1, nt, labels, B, row, lane);
}

// Generic fallback (D != 1024): warp-per-row direct global loads.
__global__ void __launch_bounds__(THREADS)
row_loss_generic_kernel(const float4* __restrict__ f0,
                        const float4* __restrict__ f1,
                        const float4* __restrict__ t,
                        const float*  __restrict__ labels,
                        int B, int D4)
{
    int gwarp = (blockIdx.x * THREADS + threadIdx.x) >> 5;
    int lane  = threadIdx.x & 31;
    if (gwarp >= B) return;

    const float4* r0 = f0 + (size_t)gwarp * D4;
    const float4* r1 = f1 + (size_t)gwarp * D4;
    const float4* rt = t  + (size_t)gwarp * D4;

    float d0 = 0.f, d1 = 0.f, n0 = 0.f, n1 = 0.f, nt = 0.f;
    for (int i = lane; i < D4; i += 32) {
        float4 a = r0[i], b = r1[i], c = rt[i];
        d0 += a.x * c.x + a.y * c.y + a.z * c.z + a.w * c.w;
        d1 += b.x * c.x + b.y * c.y + b.z * c.z + b.w * c.w;
        n0 += a.x * a.x + a.y * a.y + a.z * a.z + a.w * a.w;
        n1 += b.x * b.x + b.y * b.y + b.z * b.z + b.w * b.w;
        nt += c.x * c.x + c.y * c.y + c.z * c.z + c.w * c.w;
    }
    row_finish(d0, d1, n0, n1, nt, labels, B, gwarp, lane);
}

// Deterministic single-block reduction of the B per-row partials.
__global__ void __launch_bounds__(256)
final_reduce_kernel(float* __restrict__ out, int B)
{
    __shared__ float sdata[8];
    int tid = threadIdx.x;

    float s = 0.f;
    for (int i = tid; i < B; i += 256)
        s += g_partial[i];

    s = warp_sum(s);
    if ((tid & 31) == 0) sdata[tid >> 5] = s;
    __syncthreads();

    if (tid < 32) {
        float v = (tid < 8) ? sdata[tid] : 0.f;
#pragma unroll
        for (int o = 4; o > 0; o >>= 1)
            v += __shfl_down_sync(WARP_FULL_MASK, v, o);
        if (tid == 0)
            out[0] = v / ((float)B * (float)B);
    }
}

extern "C" void kernel_launch(void* const* d_in, const int* in_sizes, int n_in,
                              void* d_out, int out_size)
{
    const float* f0     = (const float*)d_in[0];
    const float* f1     = (const float*)d_in[1];
    const float* t      = (const float*)d_in[2];
    const float* labels = (const float*)d_in[3];

    long long nl = in_sizes[3];
    int B = (int)(sqrt((double)nl) + 0.5);
    int D = in_sizes[0] / B;
    int D4 = D / 4;

    if (D * 4 == ROW_BYTES && (B % ROWS_PER_BLOCK) == 0) {
        static int attr_set = 0;
        if (!attr_set) {
            cudaFuncSetAttribute(row_loss_tma_kernel,
                                 cudaFuncAttributeMaxDynamicSharedMemorySize,
                                 SMEM_TOTAL);
            attr_set = 1;
        }
        int blocks = B / ROWS_PER_BLOCK;   // 1024
        row_loss_tma_kernel<<<blocks, THREADS, SMEM_TOTAL>>>(
            f0, f1, t, labels, B);
    } else {
        int blocks = (B * 32 + THREADS - 1) / THREADS;
        row_loss_generic_kernel<<<blocks, THREADS>>>(
            (const float4*)f0, (const float4*)f1, (const float4*)t,
            labels, B, D4);
    }

    final_reduce_kernel<<<1, 256>>>((float*)d_out, B);
}